// round 1
// baseline (speedup 1.0000x reference)
#include <cuda_runtime.h>
#include <math.h>

#define D_MODEL 1024
#define NH 16
#define HD 64
#define BATCH 4
#define SEQ 2048
#define MTOT (BATCH*SEQ)

// Scratch: Q,K,V in [B,H,S,hd] layout; attention output in [B,S,D].
__device__ float g_q[MTOT*D_MODEL];
__device__ float g_k[MTOT*D_MODEL];
__device__ float g_v[MTOT*D_MODEL];
__device__ float g_attn[MTOT*D_MODEL];

// ---------------- Projection GEMM: C = A[M,K] @ W[N,K]^T ----------------
// 128x128 tile, BK=8, 256 threads, 8x8 micro-tile per thread.
__device__ __forceinline__ void gemm_tile(const float* __restrict__ A,
                                          const float* __restrict__ W,
                                          int m0, int n0, float acc[8][8],
                                          float (*As)[132], float (*Bs)[132])
{
    int tid = threadIdx.x;
    int lr = tid >> 1;           // 0..127
    int lk = (tid & 1) * 4;      // 0 or 4
    const float* Ap = A + (size_t)(m0 + lr) * D_MODEL + lk;
    const float* Wp = W + (size_t)(n0 + lr) * D_MODEL + lk;
    int ty = tid >> 4, tx = tid & 15;

    for (int k0 = 0; k0 < D_MODEL; k0 += 8) {
        float4 av = *(const float4*)(Ap + k0);
        float4 bv = *(const float4*)(Wp + k0);
        As[lk+0][lr] = av.x; As[lk+1][lr] = av.y;
        As[lk+2][lr] = av.z; As[lk+3][lr] = av.w;
        Bs[lk+0][lr] = bv.x; Bs[lk+1][lr] = bv.y;
        Bs[lk+2][lr] = bv.z; Bs[lk+3][lr] = bv.w;
        __syncthreads();
#pragma unroll
        for (int k = 0; k < 8; k++) {
            float a[8], b[8];
#pragma unroll
            for (int i = 0; i < 8; i++) a[i] = As[k][ty*8+i];
#pragma unroll
            for (int j = 0; j < 8; j++) b[j] = Bs[k][tx*8+j];
#pragma unroll
            for (int i = 0; i < 8; i++)
#pragma unroll
                for (int j = 0; j < 8; j++)
                    acc[i][j] = fmaf(a[i], b[j], acc[i][j]);
        }
        __syncthreads();
    }
}

__global__ __launch_bounds__(256) void qkv_kernel(const float* __restrict__ x,
    const float* __restrict__ wq, const float* __restrict__ wk,
    const float* __restrict__ wv)
{
    __shared__ float As[8][132], Bs[8][132];
    int m0 = blockIdx.x * 128;
    int nb = blockIdx.y;               // 0..23 : which weight + which 128-col slab
    const float* W; float* out;
    if (nb < 8)       { W = wq; out = g_q; }
    else if (nb < 16) { W = wk; out = g_k; nb -= 8; }
    else              { W = wv; out = g_v; nb -= 16; }
    int n0 = nb * 128;

    float acc[8][8] = {};
    gemm_tile(x, W, m0, n0, acc, As, Bs);

    int ty = threadIdx.x >> 4, tx = threadIdx.x & 15;
#pragma unroll
    for (int i = 0; i < 8; i++) {
        int m = m0 + ty*8 + i;
        int b = m / SEQ, s = m % SEQ;
#pragma unroll
        for (int j = 0; j < 8; j++) {
            int n = n0 + tx*8 + j;
            int h = n >> 6, d = n & 63;
            out[(((size_t)(b*NH + h))*SEQ + s)*HD + d] = acc[i][j];
        }
    }
}

__global__ __launch_bounds__(256) void oproj_kernel(const float* __restrict__ wo,
                                                    float* __restrict__ outp)
{
    __shared__ float As[8][132], Bs[8][132];
    int m0 = blockIdx.x * 128;
    int n0 = blockIdx.y * 128;
    float acc[8][8] = {};
    gemm_tile(g_attn, wo, m0, n0, acc, As, Bs);

    int ty = threadIdx.x >> 4, tx = threadIdx.x & 15;
#pragma unroll
    for (int i = 0; i < 8; i++) {
        size_t m = (size_t)(m0 + ty*8 + i);
#pragma unroll
        for (int j = 0; j < 8; j++)
            outp[m * D_MODEL + n0 + tx*8 + j] = acc[i][j];
    }
}

// ---------------- Causal flash attention, fp32 ----------------
// Block = 64 query rows for one (b,h). 256 threads (16x16), 4x4 micro-tiles.
__global__ __launch_bounds__(256) void attn_kernel()
{
    extern __shared__ float sm[];
    float* Qs = sm;              // [64][64]  row-major [r][d]
    float* Ks = Qs + 64*64;      // [64][65]  d-major   [d][c] (padded)
    float* Vs = Ks + 64*65;      // [64][64]  row-major [c][d]
    float* Ps = Vs + 64*64;      // [64][64]  [r][c]

    int q0 = blockIdx.x * 64;
    int bh = blockIdx.y;
    const float* Qg = g_q + (size_t)bh * SEQ * HD;
    const float* Kg = g_k + (size_t)bh * SEQ * HD;
    const float* Vg = g_v + (size_t)bh * SEQ * HD;

    int tid = threadIdx.x, ty = tid >> 4, tx = tid & 15;
    const float scale = 0.125f;  // 1/sqrt(64)

    // Load Q tile once (scaled).
    for (int t = tid; t < 1024; t += 256) {
        int r = t >> 4, d4 = (t & 15) * 4;
        float4 v = *(const float4*)(Qg + (size_t)(q0 + r) * HD + d4);
        v.x *= scale; v.y *= scale; v.z *= scale; v.w *= scale;
        *(float4*)(Qs + r*64 + d4) = v;
    }

    float m_i[4], l_i[4], acc[4][4];
#pragma unroll
    for (int i = 0; i < 4; i++) {
        m_i[i] = -1e30f; l_i[i] = 0.f;
#pragma unroll
        for (int j = 0; j < 4; j++) acc[i][j] = 0.f;
    }

    for (int k0 = 0; k0 <= q0; k0 += 64) {
        __syncthreads();   // previous-iter consumers done before overwrite
        for (int t = tid; t < 1024; t += 256) {
            int c = t >> 4, d4 = (t & 15) * 4;
            float4 kv = *(const float4*)(Kg + (size_t)(k0 + c) * HD + d4);
            Ks[(d4+0)*65 + c] = kv.x;
            Ks[(d4+1)*65 + c] = kv.y;
            Ks[(d4+2)*65 + c] = kv.z;
            Ks[(d4+3)*65 + c] = kv.w;
            *(float4*)(Vs + c*64 + d4) =
                *(const float4*)(Vg + (size_t)(k0 + c) * HD + d4);
        }
        __syncthreads();

        // S = Q @ K^T  (64x64x64 mini-GEMM)
        float s[4][4] = {};
#pragma unroll 8
        for (int d = 0; d < 64; d++) {
            float a[4], b[4];
#pragma unroll
            for (int i = 0; i < 4; i++) a[i] = Qs[(4*ty + i)*64 + d];
#pragma unroll
            for (int j = 0; j < 4; j++) b[j] = Ks[d*65 + 4*tx + j];
#pragma unroll
            for (int i = 0; i < 4; i++)
#pragma unroll
                for (int j = 0; j < 4; j++)
                    s[i][j] = fmaf(a[i], b[j], s[i][j]);
        }

        if (k0 == q0) {  // diagonal tile: causal mask
#pragma unroll
            for (int i = 0; i < 4; i++)
#pragma unroll
                for (int j = 0; j < 4; j++)
                    if (4*tx + j > 4*ty + i) s[i][j] = -1e30f;
        }

        // Online softmax. Row r = 4*ty+i is spread across the 16 lanes of a
        // tx-group (contiguous 16-lane segment), reduce via shfl width=16.
#pragma unroll
        for (int i = 0; i < 4; i++) {
            float rmax = fmaxf(fmaxf(s[i][0], s[i][1]), fmaxf(s[i][2], s[i][3]));
#pragma unroll
            for (int off = 8; off >= 1; off >>= 1)
                rmax = fmaxf(rmax, __shfl_xor_sync(0xffffffffu, rmax, off, 16));
            float nm    = fmaxf(m_i[i], rmax);
            float alpha = __expf(m_i[i] - nm);   // first iter: exp(-1e30-*) = 0
            float psum  = 0.f;
#pragma unroll
            for (int j = 0; j < 4; j++) {
                float p = __expf(s[i][j] - nm);  // masked entries underflow to 0
                s[i][j] = p;
                psum += p;
            }
#pragma unroll
            for (int off = 8; off >= 1; off >>= 1)
                psum += __shfl_xor_sync(0xffffffffu, psum, off, 16);
            l_i[i] = l_i[i] * alpha + psum;
            m_i[i] = nm;
#pragma unroll
            for (int j = 0; j < 4; j++) acc[i][j] *= alpha;
        }

#pragma unroll
        for (int i = 0; i < 4; i++)
#pragma unroll
            for (int j = 0; j < 4; j++)
                Ps[(4*ty + i)*64 + 4*tx + j] = s[i][j];
        __syncthreads();

        // O += P @ V  (64x64x64 mini-GEMM, float4 over c)
#pragma unroll
        for (int c4 = 0; c4 < 64; c4 += 4) {
            float4 pa[4], vb[4];
#pragma unroll
            for (int i = 0; i < 4; i++)
                pa[i] = *(const float4*)(Ps + (4*ty + i)*64 + c4);
#pragma unroll
            for (int cc = 0; cc < 4; cc++)
                vb[cc] = *(const float4*)(Vs + (c4 + cc)*64 + 4*tx);
#pragma unroll
            for (int i = 0; i < 4; i++) {
                float pr[4] = {pa[i].x, pa[i].y, pa[i].z, pa[i].w};
#pragma unroll
                for (int cc = 0; cc < 4; cc++) {
                    const float* vv = (const float*)&vb[cc];
#pragma unroll
                    for (int j = 0; j < 4; j++)
                        acc[i][j] = fmaf(pr[cc], vv[j], acc[i][j]);
                }
            }
        }
    }

    // Epilogue: normalize, write [B,S,D] with D = h*64 + d.
    int b = bh >> 4, h = bh & 15;
#pragma unroll
    for (int i = 0; i < 4; i++) {
        float inv = 1.0f / l_i[i];
        size_t m = (size_t)b * SEQ + q0 + 4*ty + i;
#pragma unroll
        for (int j = 0; j < 4; j++)
            g_attn[m * D_MODEL + h*64 + 4*tx + j] = acc[i][j] * inv;
    }
}

#define ATTN_SMEM ((64*64 + 64*65 + 64*64 + 64*64) * (int)sizeof(float))

extern "C" void kernel_launch(void* const* d_in, const int* in_sizes, int n_in,
                              void* d_out, int out_size)
{
    const float* x  = (const float*)d_in[0];
    const float* wq = (const float*)d_in[1];
    const float* wk = (const float*)d_in[2];
    const float* wv = (const float*)d_in[3];
    const float* wo = (const float*)d_in[4];
    float* out = (float*)d_out;

    cudaFuncSetAttribute(attn_kernel,
                         cudaFuncAttributeMaxDynamicSharedMemorySize, ATTN_SMEM);

    dim3 g1(MTOT/128, 24);      // fused QKV projection
    qkv_kernel<<<g1, 256>>>(x, wq, wk, wv);

    dim3 g2(SEQ/64, BATCH*NH);  // causal flash attention
    attn_kernel<<<g2, 256, ATTN_SMEM>>>();

    dim3 g3(MTOT/128, D_MODEL/128);  // output projection
    oproj_kernel<<<g3, 256>>>(wo, out);
}

// round 3
// speedup vs baseline: 1.8546x; 1.8546x over previous
#include <cuda_runtime.h>
#include <cuda_bf16.h>
#include <cstdint>
#include <math.h>

#define D_MODEL 1024
#define NH 16
#define HD 64
#define BATCH 4
#define SEQ 2048
#define MTOT (BATCH*SEQ)

// fp32 scratch
__device__ float g_q[MTOT*D_MODEL];
__device__ float g_k[MTOT*D_MODEL];
__device__ float g_v[MTOT*D_MODEL];
__device__ float g_attn[MTOT*D_MODEL];

// bf16 hi/lo splits
__device__ __align__(16) __nv_bfloat16 g_xh[MTOT*D_MODEL];
__device__ __align__(16) __nv_bfloat16 g_xl[MTOT*D_MODEL];
__device__ __align__(16) __nv_bfloat16 g_ah[MTOT*D_MODEL];
__device__ __align__(16) __nv_bfloat16 g_al[MTOT*D_MODEL];
__device__ __align__(16) __nv_bfloat16 g_wh[4*D_MODEL*D_MODEL];
__device__ __align__(16) __nv_bfloat16 g_wl[4*D_MODEL*D_MODEL];

// ---------------- helpers ----------------
__device__ __forceinline__ uint32_t smem_u32(const void* p) {
    uint32_t a;
    asm("{ .reg .u64 t; cvta.to.shared.u64 t, %1; cvt.u32.u64 %0, t; }"
        : "=r"(a) : "l"(p));
    return a;
}
__device__ __forceinline__ void cp16(uint32_t s, const void* g) {
    asm volatile("cp.async.ca.shared.global [%0], [%1], 16;" :: "r"(s), "l"(g));
}
__device__ __forceinline__ void ldsm_x4(uint32_t r[4], uint32_t a) {
    asm volatile("ldmatrix.sync.aligned.m8n8.x4.shared.b16 {%0,%1,%2,%3}, [%4];"
        : "=r"(r[0]), "=r"(r[1]), "=r"(r[2]), "=r"(r[3]) : "r"(a));
}
__device__ __forceinline__ void mma16816(float d[4], const uint32_t a[4],
                                         uint32_t b0, uint32_t b1) {
    asm volatile("mma.sync.aligned.m16n8k16.row.col.f32.bf16.bf16.f32 "
        "{%0,%1,%2,%3}, {%4,%5,%6,%7}, {%8,%9}, {%0,%1,%2,%3};"
        : "+f"(d[0]), "+f"(d[1]), "+f"(d[2]), "+f"(d[3])
        : "r"(a[0]), "r"(a[1]), "r"(a[2]), "r"(a[3]), "r"(b0), "r"(b1));
}

// ---------------- bf16 hi/lo split ----------------
__global__ __launch_bounds__(256) void split_kernel(const float* __restrict__ s,
    __nv_bfloat16* __restrict__ h, __nv_bfloat16* __restrict__ l, int n)
{
    int i = (blockIdx.x * 256 + threadIdx.x) * 4;
    if (i >= n) return;
    float4 v = *(const float4*)(s + i);
    float f[4] = {v.x, v.y, v.z, v.w};
    __nv_bfloat16 hh[4], ll[4];
#pragma unroll
    for (int j = 0; j < 4; j++) {
        hh[j] = __float2bfloat16(f[j]);
        ll[j] = __float2bfloat16(f[j] - __bfloat162float(hh[j]));
    }
    *(__nv_bfloat162*)(h + i)     = __nv_bfloat162(hh[0], hh[1]);
    *(__nv_bfloat162*)(h + i + 2) = __nv_bfloat162(hh[2], hh[3]);
    *(__nv_bfloat162*)(l + i)     = __nv_bfloat162(ll[0], ll[1]);
    *(__nv_bfloat162*)(l + i + 2) = __nv_bfloat162(ll[2], ll[3]);
}

// ---------------- HMMA bf16x3 GEMM: C = A[M,K] @ W[N,K]^T ----------------
// 128x128 CTA tile, BK=32, 8 warps (2x4), warp tile 64x32, double-buffered cp.async.
// SMEM tiles: 128 rows x 80B stride (32 bf16 data + pad) -> conflict-free ldmatrix.
#define TSTRIDE 80
#define TILE_B  (128*TSTRIDE)     // 10240
#define STAGE_B (4*TILE_B)        // 40960  (Ah, Al, Bh, Bl)
#define GEMM_SMEM (2*STAGE_B)     // 81920
#define NKC (D_MODEL/32)          // 32 k-chunks

__device__ __forceinline__ void load_stage(uint32_t sb, int stage, int kc,
    const __nv_bfloat16* Ah, const __nv_bfloat16* Al,
    const __nv_bfloat16* Wh, const __nv_bfloat16* Wl, int m0, int n0)
{
    int k0 = kc * 32;
    uint32_t st = sb + stage * STAGE_B;
#pragma unroll
    for (int t = 0; t < 2; t++) {
        int chunk = threadIdx.x + t * 256;       // 0..511
        int row = chunk >> 2, cc = chunk & 3;
        uint32_t so = row * TSTRIDE + cc * 16;
        size_t ga = (size_t)(m0 + row) * D_MODEL + k0 + cc * 8;
        size_t gb = (size_t)(n0 + row) * D_MODEL + k0 + cc * 8;
        cp16(st + 0*TILE_B + so, Ah + ga);
        cp16(st + 1*TILE_B + so, Al + ga);
        cp16(st + 2*TILE_B + so, Wh + gb);
        cp16(st + 3*TILE_B + so, Wl + gb);
    }
    asm volatile("cp.async.commit_group;" ::: "memory");
}

__global__ __launch_bounds__(256, 2) void mma_gemm_kernel(float* __restrict__ out_o, int mode)
{
    extern __shared__ char smem[];
    uint32_t sb = smem_u32(smem);
    int tid = threadIdx.x, wid = tid >> 5, lane = tid & 31;

    int m0 = blockIdx.x * 128;
    int nb = blockIdx.y;
    int widx, n0;
    const __nv_bfloat16 *Ah, *Al;
    if (mode == 0) { widx = nb >> 3; n0 = (nb & 7) * 128; Ah = g_xh; Al = g_xl; }
    else           { widx = 3;       n0 = nb * 128;       Ah = g_ah; Al = g_al; }
    const __nv_bfloat16* Wh = g_wh + (size_t)widx * D_MODEL * D_MODEL;
    const __nv_bfloat16* Wl = g_wl + (size_t)widx * D_MODEL * D_MODEL;

    int wm = (wid & 1) * 64;      // warp row offset in tile
    int wn = (wid >> 1) * 32;     // warp col offset in tile

    float acc[4][4][4];           // [mi][ni][frag]
#pragma unroll
    for (int i = 0; i < 4; i++)
#pragma unroll
        for (int j = 0; j < 4; j++)
#pragma unroll
            for (int r = 0; r < 4; r++) acc[i][j][r] = 0.f;

    // ldmatrix lane address components (same mapping for A and B tiles)
    int lr = lane & 15;           // row within 16-row group
    int lc = (lane >> 4) * 8;     // k-half select (0 or 8 elements)

    load_stage(sb, 0, 0, Ah, Al, Wh, Wl, m0, n0);

    int stage = 0;
    for (int kc = 0; kc < NKC; kc++) {
        if (kc + 1 < NKC) {
            load_stage(sb, stage ^ 1, kc + 1, Ah, Al, Wh, Wl, m0, n0);
            asm volatile("cp.async.wait_group 1;" ::: "memory");
        } else {
            asm volatile("cp.async.wait_group 0;" ::: "memory");
        }
        __syncthreads();

        uint32_t st = sb + stage * STAGE_B;
        uint32_t aH = st + 0*TILE_B, aL = st + 1*TILE_B;
        uint32_t bH = st + 2*TILE_B, bL = st + 3*TILE_B;

#pragma unroll
        for (int ks = 0; ks < 2; ks++) {
            int kb = ks * 16;
            uint32_t ahf[4][4], alf[4][4], bhf[2][4], blf[2][4];
#pragma unroll
            for (int mi = 0; mi < 4; mi++) {
                uint32_t ro = (uint32_t)(wm + mi*16 + lr) * TSTRIDE + (kb + lc) * 2;
                ldsm_x4(ahf[mi], aH + ro);
                ldsm_x4(alf[mi], aL + ro);
            }
#pragma unroll
            for (int p = 0; p < 2; p++) {
                uint32_t ro = (uint32_t)(wn + p*16 + lr) * TSTRIDE + (kb + lc) * 2;
                ldsm_x4(bhf[p], bH + ro);
                ldsm_x4(blf[p], bL + ro);
            }
#pragma unroll
            for (int mi = 0; mi < 4; mi++)
#pragma unroll
                for (int ni = 0; ni < 4; ni++) {
                    int p = ni >> 1, h = ni & 1;
                    mma16816(acc[mi][ni], ahf[mi], bhf[p][h], bhf[p][h+2]); // Ah*Bh
                    mma16816(acc[mi][ni], alf[mi], bhf[p][h], bhf[p][h+2]); // Al*Bh
                    mma16816(acc[mi][ni], ahf[mi], blf[p][h], blf[p][h+2]); // Ah*Bl
                }
        }
        stage ^= 1;
        __syncthreads();   // all warps done with this stage before it's overwritten
    }

    // Epilogue
    int qr = lane >> 2, qc = (lane & 3) * 2;
#pragma unroll
    for (int mi = 0; mi < 4; mi++) {
#pragma unroll
        for (int ni = 0; ni < 4; ni++) {
            int r0 = m0 + wm + mi*16 + qr;
            int cN = n0 + wn + ni*8 + qc;
            if (mode == 0) {
                float* outp = (widx == 0) ? g_q : (widx == 1) ? g_k : g_v;
                int h = cN >> 6, d = cN & 63;
                int b0r = r0 / SEQ, s0 = r0 % SEQ;
                int b1r = (r0+8) / SEQ, s1 = (r0+8) % SEQ;
                float2* p0 = (float2*)(outp + (((size_t)(b0r*NH + h))*SEQ + s0)*HD + d);
                float2* p1 = (float2*)(outp + (((size_t)(b1r*NH + h))*SEQ + s1)*HD + d);
                *p0 = make_float2(acc[mi][ni][0], acc[mi][ni][1]);
                *p1 = make_float2(acc[mi][ni][2], acc[mi][ni][3]);
            } else {
                float2* p0 = (float2*)(out_o + (size_t)r0 * D_MODEL + cN);
                float2* p1 = (float2*)(out_o + (size_t)(r0+8) * D_MODEL + cN);
                *p0 = make_float2(acc[mi][ni][0], acc[mi][ni][1]);
                *p1 = make_float2(acc[mi][ni][2], acc[mi][ni][3]);
            }
        }
    }
}

// ---------------- Causal flash attention, fp32 (unchanged, passing) ----------------
__global__ __launch_bounds__(256) void attn_kernel()
{
    extern __shared__ float sm[];
    float* Qs = sm;
    float* Ks = Qs + 64*64;
    float* Vs = Ks + 64*65;
    float* Ps = Vs + 64*64;

    int q0 = blockIdx.x * 64;
    int bh = blockIdx.y;
    const float* Qg = g_q + (size_t)bh * SEQ * HD;
    const float* Kg = g_k + (size_t)bh * SEQ * HD;
    const float* Vg = g_v + (size_t)bh * SEQ * HD;

    int tid = threadIdx.x, ty = tid >> 4, tx = tid & 15;
    const float scale = 0.125f;

    for (int t = tid; t < 1024; t += 256) {
        int r = t >> 4, d4 = (t & 15) * 4;
        float4 v = *(const float4*)(Qg + (size_t)(q0 + r) * HD + d4);
        v.x *= scale; v.y *= scale; v.z *= scale; v.w *= scale;
        *(float4*)(Qs + r*64 + d4) = v;
    }

    float m_i[4], l_i[4], acc[4][4];
#pragma unroll
    for (int i = 0; i < 4; i++) {
        m_i[i] = -1e30f; l_i[i] = 0.f;
#pragma unroll
        for (int j = 0; j < 4; j++) acc[i][j] = 0.f;
    }

    for (int k0 = 0; k0 <= q0; k0 += 64) {
        __syncthreads();
        for (int t = tid; t < 1024; t += 256) {
            int c = t >> 4, d4 = (t & 15) * 4;
            float4 kv = *(const float4*)(Kg + (size_t)(k0 + c) * HD + d4);
            Ks[(d4+0)*65 + c] = kv.x;
            Ks[(d4+1)*65 + c] = kv.y;
            Ks[(d4+2)*65 + c] = kv.z;
            Ks[(d4+3)*65 + c] = kv.w;
            *(float4*)(Vs + c*64 + d4) =
                *(const float4*)(Vg + (size_t)(k0 + c) * HD + d4);
        }
        __syncthreads();

        float s[4][4] = {};
#pragma unroll 8
        for (int d = 0; d < 64; d++) {
            float a[4], b[4];
#pragma unroll
            for (int i = 0; i < 4; i++) a[i] = Qs[(4*ty + i)*64 + d];
#pragma unroll
            for (int j = 0; j < 4; j++) b[j] = Ks[d*65 + 4*tx + j];
#pragma unroll
            for (int i = 0; i < 4; i++)
#pragma unroll
                for (int j = 0; j < 4; j++)
                    s[i][j] = fmaf(a[i], b[j], s[i][j]);
        }

        if (k0 == q0) {
#pragma unroll
            for (int i = 0; i < 4; i++)
#pragma unroll
                for (int j = 0; j < 4; j++)
                    if (4*tx + j > 4*ty + i) s[i][j] = -1e30f;
        }

#pragma unroll
        for (int i = 0; i < 4; i++) {
            float rmax = fmaxf(fmaxf(s[i][0], s[i][1]), fmaxf(s[i][2], s[i][3]));
#pragma unroll
            for (int off = 8; off >= 1; off >>= 1)
                rmax = fmaxf(rmax, __shfl_xor_sync(0xffffffffu, rmax, off, 16));
            float nm    = fmaxf(m_i[i], rmax);
            float alpha = __expf(m_i[i] - nm);
            float psum  = 0.f;
#pragma unroll
            for (int j = 0; j < 4; j++) {
                float p = __expf(s[i][j] - nm);
                s[i][j] = p;
                psum += p;
            }
#pragma unroll
            for (int off = 8; off >= 1; off >>= 1)
                psum += __shfl_xor_sync(0xffffffffu, psum, off, 16);
            l_i[i] = l_i[i] * alpha + psum;
            m_i[i] = nm;
#pragma unroll
            for (int j = 0; j < 4; j++) acc[i][j] *= alpha;
        }

#pragma unroll
        for (int i = 0; i < 4; i++)
#pragma unroll
            for (int j = 0; j < 4; j++)
                Ps[(4*ty + i)*64 + 4*tx + j] = s[i][j];
        __syncthreads();

#pragma unroll
        for (int c4 = 0; c4 < 64; c4 += 4) {
            float4 pa[4], vb[4];
#pragma unroll
            for (int i = 0; i < 4; i++)
                pa[i] = *(const float4*)(Ps + (4*ty + i)*64 + c4);
#pragma unroll
            for (int cc = 0; cc < 4; cc++)
                vb[cc] = *(const float4*)(Vs + (c4 + cc)*64 + 4*tx);
#pragma unroll
            for (int i = 0; i < 4; i++) {
                float pr[4] = {pa[i].x, pa[i].y, pa[i].z, pa[i].w};
#pragma unroll
                for (int cc = 0; cc < 4; cc++) {
                    const float* vv = (const float*)&vb[cc];
#pragma unroll
                    for (int j = 0; j < 4; j++)
                        acc[i][j] = fmaf(pr[cc], vv[j], acc[i][j]);
                }
            }
        }
    }

    int b = bh >> 4, h = bh & 15;
#pragma unroll
    for (int i = 0; i < 4; i++) {
        float inv = 1.0f / l_i[i];
        size_t m = (size_t)b * SEQ + q0 + 4*ty + i;
#pragma unroll
        for (int j = 0; j < 4; j++)
            g_attn[m * D_MODEL + h*64 + 4*tx + j] = acc[i][j] * inv;
    }
}

#define ATTN_SMEM ((64*64 + 64*65 + 64*64 + 64*64) * (int)sizeof(float))

extern "C" void kernel_launch(void* const* d_in, const int* in_sizes, int n_in,
                              void* d_out, int out_size)
{
    const float* x  = (const float*)d_in[0];
    const float* wq = (const float*)d_in[1];
    const float* wk = (const float*)d_in[2];
    const float* wv = (const float*)d_in[3];
    const float* wo = (const float*)d_in[4];
    float* out = (float*)d_out;

    cudaFuncSetAttribute(attn_kernel,
                         cudaFuncAttributeMaxDynamicSharedMemorySize, ATTN_SMEM);
    cudaFuncSetAttribute(mma_gemm_kernel,
                         cudaFuncAttributeMaxDynamicSharedMemorySize, GEMM_SMEM);

    __nv_bfloat16 *xh, *xl, *ah, *al, *wh, *wl;
    cudaGetSymbolAddress((void**)&xh, g_xh);
    cudaGetSymbolAddress((void**)&xl, g_xl);
    cudaGetSymbolAddress((void**)&ah, g_ah);
    cudaGetSymbolAddress((void**)&al, g_al);
    cudaGetSymbolAddress((void**)&wh, g_wh);
    cudaGetSymbolAddress((void**)&wl, g_wl);
    float* attn_f;
    cudaGetSymbolAddress((void**)&attn_f, g_attn);

    const int NX = MTOT * D_MODEL;          // 8.4M
    const int NW = D_MODEL * D_MODEL;       // 1.05M

    split_kernel<<<NX/4/256, 256>>>(x, xh, xl, NX);
    split_kernel<<<NW/4/256, 256>>>(wq, wh + 0*(size_t)NW, wl + 0*(size_t)NW, NW);
    split_kernel<<<NW/4/256, 256>>>(wk, wh + 1*(size_t)NW, wl + 1*(size_t)NW, NW);
    split_kernel<<<NW/4/256, 256>>>(wv, wh + 2*(size_t)NW, wl + 2*(size_t)NW, NW);
    split_kernel<<<NW/4/256, 256>>>(wo, wh + 3*(size_t)NW, wl + 3*(size_t)NW, NW);

    // QKV projection on HMMA (bf16x3)
    dim3 g1(MTOT/128, 24);
    mma_gemm_kernel<<<g1, 256, GEMM_SMEM>>>(nullptr, 0);

    // causal flash attention (fp32)
    dim3 g2(SEQ/64, BATCH*NH);
    attn_kernel<<<g2, 256, ATTN_SMEM>>>();

    // split attention output, then O-projection on HMMA
    split_kernel<<<NX/4/256, 256>>>(attn_f, ah, al, NX);
    dim3 g3(MTOT/128, D_MODEL/128);
    mma_gemm_kernel<<<g3, 256, GEMM_SMEM>>>(out, 1);
}

// round 4
// speedup vs baseline: 3.1148x; 1.6795x over previous
#include <cuda_runtime.h>
#include <cuda_bf16.h>
#include <cstdint>
#include <math.h>

#define D_MODEL 1024
#define NH 16
#define HD 64
#define BATCH 4
#define SEQ 2048
#define MTOT (BATCH*SEQ)

// bf16 hi/lo scratch
__device__ __align__(16) __nv_bfloat16 g_xh[MTOT*D_MODEL];
__device__ __align__(16) __nv_bfloat16 g_xl[MTOT*D_MODEL];
__device__ __align__(16) __nv_bfloat16 g_ah[MTOT*D_MODEL];   // attention out hi
__device__ __align__(16) __nv_bfloat16 g_al[MTOT*D_MODEL];   // attention out lo
__device__ __align__(16) __nv_bfloat16 g_wh[4*D_MODEL*D_MODEL];
__device__ __align__(16) __nv_bfloat16 g_wl[4*D_MODEL*D_MODEL];
// QKV in bf16 hi/lo; Q pre-scaled by 1/8; V stored transposed [b,h,d,s]
__device__ __align__(16) __nv_bfloat16 g_qh[MTOT*D_MODEL];
__device__ __align__(16) __nv_bfloat16 g_ql[MTOT*D_MODEL];
__device__ __align__(16) __nv_bfloat16 g_kh[MTOT*D_MODEL];
__device__ __align__(16) __nv_bfloat16 g_kl[MTOT*D_MODEL];
__device__ __align__(16) __nv_bfloat16 g_vth[MTOT*D_MODEL];
__device__ __align__(16) __nv_bfloat16 g_vtl[MTOT*D_MODEL];

// ---------------- helpers ----------------
__device__ __forceinline__ uint32_t smem_u32(const void* p) {
    uint32_t a;
    asm("{ .reg .u64 t; cvta.to.shared.u64 t, %1; cvt.u32.u64 %0, t; }"
        : "=r"(a) : "l"(p));
    return a;
}
__device__ __forceinline__ void cp16(uint32_t s, const void* g) {
    asm volatile("cp.async.ca.shared.global [%0], [%1], 16;" :: "r"(s), "l"(g));
}
__device__ __forceinline__ void ldsm_x4(uint32_t r[4], uint32_t a) {
    asm volatile("ldmatrix.sync.aligned.m8n8.x4.shared.b16 {%0,%1,%2,%3}, [%4];"
        : "=r"(r[0]), "=r"(r[1]), "=r"(r[2]), "=r"(r[3]) : "r"(a));
}
__device__ __forceinline__ void mma16816(float d[4], const uint32_t a[4],
                                         uint32_t b0, uint32_t b1) {
    asm volatile("mma.sync.aligned.m16n8k16.row.col.f32.bf16.bf16.f32 "
        "{%0,%1,%2,%3}, {%4,%5,%6,%7}, {%8,%9}, {%0,%1,%2,%3};"
        : "+f"(d[0]), "+f"(d[1]), "+f"(d[2]), "+f"(d[3])
        : "r"(a[0]), "r"(a[1]), "r"(a[2]), "r"(a[3]), "r"(b0), "r"(b1));
}
// pack high-16 bits of two fp32 -> bf16x2 (low = x0). Truncation split.
__device__ __forceinline__ uint32_t pack_hi(float x0, float x1) {
    uint32_t r;
    asm("prmt.b32 %0, %1, %2, 0x7632;" : "=r"(r)
        : "r"(__float_as_uint(x0)), "r"(__float_as_uint(x1)));
    return r;
}
__device__ __forceinline__ uint32_t pack_lo(float x0, float x1) {
    float h0 = __uint_as_float(__float_as_uint(x0) & 0xFFFF0000u);
    float h1 = __uint_as_float(__float_as_uint(x1) & 0xFFFF0000u);
    uint32_t r;
    asm("cvt.rn.bf16x2.f32 %0, %1, %2;" : "=r"(r) : "f"(x1 - h1), "f"(x0 - h0));
    return r;
}
__device__ __forceinline__ void store_hl(__nv_bfloat16* H, __nv_bfloat16* L,
                                         size_t idx, float v) {
    uint32_t b = __float_as_uint(v);
    *(uint16_t*)(H + idx) = (uint16_t)(b >> 16);
    float hf = __uint_as_float(b & 0xFFFF0000u);
    L[idx] = __float2bfloat16_rn(v - hf);
}

// ---------------- bf16 hi/lo split ----------------
__global__ __launch_bounds__(256) void split_kernel(const float* __restrict__ s,
    __nv_bfloat16* __restrict__ h, __nv_bfloat16* __restrict__ l, int n)
{
    int i = (blockIdx.x * 256 + threadIdx.x) * 4;
    if (i >= n) return;
    float4 v = *(const float4*)(s + i);
    *(uint32_t*)(h + i)     = pack_hi(v.x, v.y);
    *(uint32_t*)(h + i + 2) = pack_hi(v.z, v.w);
    *(uint32_t*)(l + i)     = pack_lo(v.x, v.y);
    *(uint32_t*)(l + i + 2) = pack_lo(v.z, v.w);
}

// ---------------- HMMA bf16x3 GEMM: C = A[M,K] @ W[N,K]^T ----------------
#define TSTRIDE 80
#define TILE_B  (128*TSTRIDE)
#define STAGE_B (4*TILE_B)
#define GEMM_SMEM (2*STAGE_B)
#define NKC (D_MODEL/32)

__device__ __forceinline__ void load_stage(uint32_t sb, int stage, int kc,
    const __nv_bfloat16* Ah, const __nv_bfloat16* Al,
    const __nv_bfloat16* Wh, const __nv_bfloat16* Wl, int m0, int n0)
{
    int k0 = kc * 32;
    uint32_t st = sb + stage * STAGE_B;
#pragma unroll
    for (int t = 0; t < 2; t++) {
        int chunk = threadIdx.x + t * 256;
        int row = chunk >> 2, cc = chunk & 3;
        uint32_t so = row * TSTRIDE + cc * 16;
        size_t ga = (size_t)(m0 + row) * D_MODEL + k0 + cc * 8;
        size_t gb = (size_t)(n0 + row) * D_MODEL + k0 + cc * 8;
        cp16(st + 0*TILE_B + so, Ah + ga);
        cp16(st + 1*TILE_B + so, Al + ga);
        cp16(st + 2*TILE_B + so, Wh + gb);
        cp16(st + 3*TILE_B + so, Wl + gb);
    }
    asm volatile("cp.async.commit_group;" ::: "memory");
}

__global__ __launch_bounds__(256, 2) void mma_gemm_kernel(float* __restrict__ out_o, int mode)
{
    extern __shared__ char smem[];
    uint32_t sb = smem_u32(smem);
    int tid = threadIdx.x, wid = tid >> 5, lane = tid & 31;

    int m0 = blockIdx.x * 128;
    int nb = blockIdx.y;
    int widx, n0;
    const __nv_bfloat16 *Ah, *Al;
    if (mode == 0) { widx = nb >> 3; n0 = (nb & 7) * 128; Ah = g_xh; Al = g_xl; }
    else           { widx = 3;       n0 = nb * 128;       Ah = g_ah; Al = g_al; }
    const __nv_bfloat16* Wh = g_wh + (size_t)widx * D_MODEL * D_MODEL;
    const __nv_bfloat16* Wl = g_wl + (size_t)widx * D_MODEL * D_MODEL;

    int wm = (wid & 1) * 64;
    int wn = (wid >> 1) * 32;

    float acc[4][4][4];
#pragma unroll
    for (int i = 0; i < 4; i++)
#pragma unroll
        for (int j = 0; j < 4; j++)
#pragma unroll
            for (int r = 0; r < 4; r++) acc[i][j][r] = 0.f;

    int lr = lane & 15;
    int lc = (lane >> 4) * 8;

    load_stage(sb, 0, 0, Ah, Al, Wh, Wl, m0, n0);

    int stage = 0;
    for (int kc = 0; kc < NKC; kc++) {
        if (kc + 1 < NKC) {
            load_stage(sb, stage ^ 1, kc + 1, Ah, Al, Wh, Wl, m0, n0);
            asm volatile("cp.async.wait_group 1;" ::: "memory");
        } else {
            asm volatile("cp.async.wait_group 0;" ::: "memory");
        }
        __syncthreads();

        uint32_t st = sb + stage * STAGE_B;
        uint32_t aH = st + 0*TILE_B, aL = st + 1*TILE_B;
        uint32_t bH = st + 2*TILE_B, bL = st + 3*TILE_B;

#pragma unroll
        for (int ks = 0; ks < 2; ks++) {
            int kb = ks * 16;
            uint32_t ahf[4][4], alf[4][4], bhf[2][4], blf[2][4];
#pragma unroll
            for (int mi = 0; mi < 4; mi++) {
                uint32_t ro = (uint32_t)(wm + mi*16 + lr) * TSTRIDE + (kb + lc) * 2;
                ldsm_x4(ahf[mi], aH + ro);
                ldsm_x4(alf[mi], aL + ro);
            }
#pragma unroll
            for (int p = 0; p < 2; p++) {
                uint32_t ro = (uint32_t)(wn + p*16 + lr) * TSTRIDE + (kb + lc) * 2;
                ldsm_x4(bhf[p], bH + ro);
                ldsm_x4(blf[p], bL + ro);
            }
#pragma unroll
            for (int mi = 0; mi < 4; mi++)
#pragma unroll
                for (int ni = 0; ni < 4; ni++) {
                    int p = ni >> 1, h = ni & 1;
                    mma16816(acc[mi][ni], ahf[mi], bhf[p][h], bhf[p][h+2]);
                    mma16816(acc[mi][ni], alf[mi], bhf[p][h], bhf[p][h+2]);
                    mma16816(acc[mi][ni], ahf[mi], blf[p][h], blf[p][h+2]);
                }
        }
        stage ^= 1;
        __syncthreads();
    }

    // Epilogue
    int qr = lane >> 2, qc = (lane & 3) * 2;
    float scl = (mode == 0 && widx == 0) ? 0.125f : 1.f;
#pragma unroll
    for (int mi = 0; mi < 4; mi++) {
#pragma unroll
        for (int ni = 0; ni < 4; ni++) {
            int r0 = m0 + wm + mi*16 + qr;
            int cN = n0 + wn + ni*8 + qc;
            float v0 = acc[mi][ni][0]*scl, v1 = acc[mi][ni][1]*scl;
            float v2 = acc[mi][ni][2]*scl, v3 = acc[mi][ni][3]*scl;
            if (mode == 0) {
                int h = cN >> 6, d = cN & 63;
                int b0 = r0 / SEQ, ss = r0 % SEQ;
                if (widx == 0) {
                    size_t a0 = (((size_t)(b0*NH + h))*SEQ + ss)*HD + d;
                    size_t a1 = a0 + 8*HD;
                    *(uint32_t*)(g_qh + a0) = pack_hi(v0, v1);
                    *(uint32_t*)(g_ql + a0) = pack_lo(v0, v1);
                    *(uint32_t*)(g_qh + a1) = pack_hi(v2, v3);
                    *(uint32_t*)(g_ql + a1) = pack_lo(v2, v3);
                } else if (widx == 1) {
                    size_t a0 = (((size_t)(b0*NH + h))*SEQ + ss)*HD + d;
                    size_t a1 = a0 + 8*HD;
                    *(uint32_t*)(g_kh + a0) = pack_hi(v0, v1);
                    *(uint32_t*)(g_kl + a0) = pack_lo(v0, v1);
                    *(uint32_t*)(g_kh + a1) = pack_hi(v2, v3);
                    *(uint32_t*)(g_kl + a1) = pack_lo(v2, v3);
                } else {
                    // V transposed: [b,h,d,s]
                    size_t base = ((size_t)(b0*NH + h)) * HD;
                    store_hl(g_vth, g_vtl, (base + d  )*SEQ + ss,     v0);
                    store_hl(g_vth, g_vtl, (base + d+1)*SEQ + ss,     v1);
                    store_hl(g_vth, g_vtl, (base + d  )*SEQ + ss + 8, v2);
                    store_hl(g_vth, g_vtl, (base + d+1)*SEQ + ss + 8, v3);
                }
            } else {
                float2* p0 = (float2*)(out_o + (size_t)r0 * D_MODEL + cN);
                float2* p1 = (float2*)(out_o + (size_t)(r0+8) * D_MODEL + cN);
                *p0 = make_float2(v0, v1);
                *p1 = make_float2(v2, v3);
            }
        }
    }
}

// ---------------- HMMA bf16x3 causal flash attention ----------------
// 128 q-rows per CTA, 8 warps x 16 rows, kv tiles of 128, double-buffered.
#define QSTR 144
#define KSTR 144
#define VSTR 272
#define AQ_H 0
#define AQ_L 18432
#define AK_BASE 36864
#define KBUF_SZ 71680        // Kh 18432 + Kl 18432 + Vth 17408 + Vtl 17408
#define ATTN_SMEM (AK_BASE + 2*KBUF_SZ)   // 180224

__device__ __forceinline__ void attn_load_kv(uint32_t sb, int buf, int t, int tid,
    const __nv_bfloat16* Kh, const __nv_bfloat16* Kl,
    const __nv_bfloat16* Vth, const __nv_bfloat16* Vtl)
{
    uint32_t kb = sb + AK_BASE + buf * KBUF_SZ;
#pragma unroll
    for (int p = 0; p < 4; p++) {
        int i = tid + p*256;          // 0..1023
        int row = i >> 3, c = i & 7;
        size_t g = (size_t)(t*128 + row)*HD + c*8;
        cp16(kb + row*KSTR + c*16, Kh + g);
        cp16(kb + 18432 + row*KSTR + c*16, Kl + g);
    }
#pragma unroll
    for (int p = 0; p < 4; p++) {
        int i = tid + p*256;
        int d = i >> 4, c = i & 15;
        size_t g = (size_t)d*SEQ + t*128 + c*8;
        cp16(kb + 36864 + d*VSTR + c*16, Vth + g);
        cp16(kb + 54272 + d*VSTR + c*16, Vtl + g);
    }
    asm volatile("cp.async.commit_group;" ::: "memory");
}

__global__ __launch_bounds__(256) void attn_mma_kernel()
{
    extern __shared__ char smem[];
    uint32_t sb = smem_u32(smem);
    int tid = threadIdx.x, wid = tid >> 5, lane = tid & 31;
    int qb = blockIdx.x, q0 = qb * 128, bh = blockIdx.y;

    const __nv_bfloat16* Qh  = g_qh  + (size_t)bh * SEQ * HD;
    const __nv_bfloat16* Ql  = g_ql  + (size_t)bh * SEQ * HD;
    const __nv_bfloat16* Kh  = g_kh  + (size_t)bh * SEQ * HD;
    const __nv_bfloat16* Kl  = g_kl  + (size_t)bh * SEQ * HD;
    const __nv_bfloat16* Vth = g_vth + (size_t)bh * HD * SEQ;
    const __nv_bfloat16* Vtl = g_vtl + (size_t)bh * HD * SEQ;

    // Q tile load (group 0)
#pragma unroll
    for (int p = 0; p < 4; p++) {
        int i = tid + p*256;
        int row = i >> 3, c = i & 7;
        size_t g = (size_t)(q0 + row)*HD + c*8;
        cp16(sb + AQ_H + row*QSTR + c*16, Qh + g);
        cp16(sb + AQ_L + row*QSTR + c*16, Ql + g);
    }
    asm volatile("cp.async.commit_group;" ::: "memory");

    attn_load_kv(sb, 0, 0, tid, Kh, Kl, Vth, Vtl);

    int lr = lane & 15, lc = (lane >> 4) * 8;
    float o[8][4];
#pragma unroll
    for (int j = 0; j < 8; j++)
#pragma unroll
        for (int e = 0; e < 4; e++) o[j][e] = 0.f;
    float m0r = -1e30f, m1r = -1e30f, l0 = 0.f, l1 = 0.f;

    int buf = 0;
    for (int t = 0; t <= qb; t++) {
        if (t < qb) {
            attn_load_kv(sb, buf ^ 1, t + 1, tid, Kh, Kl, Vth, Vtl);
            asm volatile("cp.async.wait_group 1;" ::: "memory");
        } else {
            asm volatile("cp.async.wait_group 0;" ::: "memory");
        }
        __syncthreads();
        uint32_t kb = sb + AK_BASE + buf * KBUF_SZ;

        // Q fragments (reload per iter; cheap, saves registers)
        uint32_t aqh[4][4], aql[4][4];
#pragma unroll
        for (int kd = 0; kd < 4; kd++) {
            uint32_t ro = (uint32_t)(wid*16 + lr) * QSTR + (kd*16 + lc) * 2;
            ldsm_x4(aqh[kd], sb + AQ_H + ro);
            ldsm_x4(aql[kd], sb + AQ_L + ro);
        }

        // S = Q K^T (bf16x3)
        float s[16][4];
#pragma unroll
        for (int j = 0; j < 16; j++)
#pragma unroll
            for (int e = 0; e < 4; e++) s[j][e] = 0.f;
#pragma unroll
        for (int p = 0; p < 8; p++) {
#pragma unroll
            for (int kd = 0; kd < 4; kd++) {
                uint32_t bh4[4], bl4[4];
                uint32_t ro = (uint32_t)(p*16 + lr) * KSTR + (kd*16 + lc) * 2;
                ldsm_x4(bh4, kb + ro);
                ldsm_x4(bl4, kb + 18432 + ro);
#pragma unroll
                for (int h = 0; h < 2; h++) {
                    mma16816(s[2*p+h], aqh[kd], bh4[h], bh4[h+2]);
                    mma16816(s[2*p+h], aql[kd], bh4[h], bh4[h+2]);
                    mma16816(s[2*p+h], aqh[kd], bl4[h], bl4[h+2]);
                }
            }
        }

        // causal mask on diagonal tile
        if (t == qb) {
            int r0l = wid*16 + (lane >> 2);
            int r1l = r0l + 8;
#pragma unroll
            for (int j = 0; j < 16; j++) {
                int c0 = 8*j + 2*(lane & 3);
                if (c0     > r0l) s[j][0] = -1e30f;
                if (c0 + 1 > r0l) s[j][1] = -1e30f;
                if (c0     > r1l) s[j][2] = -1e30f;
                if (c0 + 1 > r1l) s[j][3] = -1e30f;
            }
        }

        // online softmax (rows qr, qr+8; 4 lanes per row)
        float rm0 = -1e30f, rm1 = -1e30f;
#pragma unroll
        for (int j = 0; j < 16; j++) {
            rm0 = fmaxf(rm0, fmaxf(s[j][0], s[j][1]));
            rm1 = fmaxf(rm1, fmaxf(s[j][2], s[j][3]));
        }
        rm0 = fmaxf(rm0, __shfl_xor_sync(0xffffffffu, rm0, 1));
        rm0 = fmaxf(rm0, __shfl_xor_sync(0xffffffffu, rm0, 2));
        rm1 = fmaxf(rm1, __shfl_xor_sync(0xffffffffu, rm1, 1));
        rm1 = fmaxf(rm1, __shfl_xor_sync(0xffffffffu, rm1, 2));
        float mn0 = fmaxf(m0r, rm0), mn1 = fmaxf(m1r, rm1);
        float a0 = __expf(m0r - mn0), a1 = __expf(m1r - mn1);
        float sum0 = 0.f, sum1 = 0.f;
#pragma unroll
        for (int j = 0; j < 16; j++) {
            s[j][0] = __expf(s[j][0] - mn0);
            s[j][1] = __expf(s[j][1] - mn0);
            s[j][2] = __expf(s[j][2] - mn1);
            s[j][3] = __expf(s[j][3] - mn1);
            sum0 += s[j][0] + s[j][1];
            sum1 += s[j][2] + s[j][3];
        }
        sum0 += __shfl_xor_sync(0xffffffffu, sum0, 1);
        sum0 += __shfl_xor_sync(0xffffffffu, sum0, 2);
        sum1 += __shfl_xor_sync(0xffffffffu, sum1, 1);
        sum1 += __shfl_xor_sync(0xffffffffu, sum1, 2);
        l0 = l0 * a0 + sum0;  l1 = l1 * a1 + sum1;
        m0r = mn0;  m1r = mn1;
#pragma unroll
        for (int j = 0; j < 8; j++) {
            o[j][0] *= a0; o[j][1] *= a0; o[j][2] *= a1; o[j][3] *= a1;
        }

        // pack P (hi/lo) as A-fragments
        uint32_t ph[8][4], pl[8][4];
#pragma unroll
        for (int kk = 0; kk < 8; kk++) {
            ph[kk][0] = pack_hi(s[2*kk][0],   s[2*kk][1]);
            ph[kk][1] = pack_hi(s[2*kk][2],   s[2*kk][3]);
            ph[kk][2] = pack_hi(s[2*kk+1][0], s[2*kk+1][1]);
            ph[kk][3] = pack_hi(s[2*kk+1][2], s[2*kk+1][3]);
            pl[kk][0] = pack_lo(s[2*kk][0],   s[2*kk][1]);
            pl[kk][1] = pack_lo(s[2*kk][2],   s[2*kk][3]);
            pl[kk][2] = pack_lo(s[2*kk+1][0], s[2*kk+1][1]);
            pl[kk][3] = pack_lo(s[2*kk+1][2], s[2*kk+1][3]);
        }

        // O += P @ V (bf16x3, V^T tiles, non-trans ldsm)
#pragma unroll
        for (int pd = 0; pd < 4; pd++) {
#pragma unroll
            for (int kk = 0; kk < 8; kk++) {
                uint32_t vh4[4], vl4[4];
                uint32_t ro = (uint32_t)(pd*16 + lr) * VSTR + (kk*16 + lc) * 2;
                ldsm_x4(vh4, kb + 36864 + ro);
                ldsm_x4(vl4, kb + 54272 + ro);
#pragma unroll
                for (int h = 0; h < 2; h++) {
                    mma16816(o[2*pd+h], ph[kk], vh4[h], vh4[h+2]);
                    mma16816(o[2*pd+h], pl[kk], vh4[h], vh4[h+2]);
                    mma16816(o[2*pd+h], ph[kk], vl4[h], vl4[h+2]);
                }
            }
        }
        __syncthreads();
        buf ^= 1;
    }

    // epilogue: normalize, hi/lo split, write [B,S,D]
    float i0 = 1.f / l0, i1 = 1.f / l1;
    int b = bh >> 4, h = bh & 15;
    int s0 = q0 + wid*16 + (lane >> 2);
#pragma unroll
    for (int j = 0; j < 8; j++) {
        int d = h*64 + 8*j + 2*(lane & 3);
        float v0 = o[j][0]*i0, v1 = o[j][1]*i0;
        float v2 = o[j][2]*i1, v3 = o[j][3]*i1;
        size_t a0 = ((size_t)b*SEQ + s0) * D_MODEL + d;
        size_t a1 = a0 + (size_t)8 * D_MODEL;
        *(uint32_t*)(g_ah + a0) = pack_hi(v0, v1);
        *(uint32_t*)(g_al + a0) = pack_lo(v0, v1);
        *(uint32_t*)(g_ah + a1) = pack_hi(v2, v3);
        *(uint32_t*)(g_al + a1) = pack_lo(v2, v3);
    }
}

extern "C" void kernel_launch(void* const* d_in, const int* in_sizes, int n_in,
                              void* d_out, int out_size)
{
    const float* x  = (const float*)d_in[0];
    const float* wq = (const float*)d_in[1];
    const float* wk = (const float*)d_in[2];
    const float* wv = (const float*)d_in[3];
    const float* wo = (const float*)d_in[4];
    float* out = (float*)d_out;

    cudaFuncSetAttribute(mma_gemm_kernel,
                         cudaFuncAttributeMaxDynamicSharedMemorySize, GEMM_SMEM);
    cudaFuncSetAttribute(attn_mma_kernel,
                         cudaFuncAttributeMaxDynamicSharedMemorySize, ATTN_SMEM);

    __nv_bfloat16 *xh, *xl, *wh, *wl;
    cudaGetSymbolAddress((void**)&xh, g_xh);
    cudaGetSymbolAddress((void**)&xl, g_xl);
    cudaGetSymbolAddress((void**)&wh, g_wh);
    cudaGetSymbolAddress((void**)&wl, g_wl);

    const int NX = MTOT * D_MODEL;
    const int NW = D_MODEL * D_MODEL;

    split_kernel<<<NX/4/256, 256>>>(x, xh, xl, NX);
    split_kernel<<<NW/4/256, 256>>>(wq, wh + 0*(size_t)NW, wl + 0*(size_t)NW, NW);
    split_kernel<<<NW/4/256, 256>>>(wk, wh + 1*(size_t)NW, wl + 1*(size_t)NW, NW);
    split_kernel<<<NW/4/256, 256>>>(wv, wh + 2*(size_t)NW, wl + 2*(size_t)NW, NW);
    split_kernel<<<NW/4/256, 256>>>(wo, wh + 3*(size_t)NW, wl + 3*(size_t)NW, NW);

    // QKV projection (writes bf16 hi/lo Q,K scaled + V transposed)
    dim3 g1(MTOT/128, 24);
    mma_gemm_kernel<<<g1, 256, GEMM_SMEM>>>(nullptr, 0);

    // tensor-core causal flash attention (writes bf16 hi/lo attn output)
    dim3 g2(SEQ/128, BATCH*NH);
    attn_mma_kernel<<<g2, 256, ATTN_SMEM>>>();

    // O-projection
    dim3 g3(MTOT/128, D_MODEL/128);
    mma_gemm_kernel<<<g3, 256, GEMM_SMEM>>>(out, 1);
}

// round 5
// speedup vs baseline: 3.1180x; 1.0010x over previous
#include <cuda_runtime.h>
#include <cuda_bf16.h>
#include <cstdint>
#include <math.h>

#define D_MODEL 1024
#define NH 16
#define HD 64
#define BATCH 4
#define SEQ 2048
#define MTOT (BATCH*SEQ)

// bf16 hi/lo scratch
__device__ __align__(16) __nv_bfloat16 g_xh[MTOT*D_MODEL];
__device__ __align__(16) __nv_bfloat16 g_xl[MTOT*D_MODEL];
__device__ __align__(16) __nv_bfloat16 g_ah[MTOT*D_MODEL];   // attention out hi
__device__ __align__(16) __nv_bfloat16 g_al[MTOT*D_MODEL];   // attention out lo
__device__ __align__(16) __nv_bfloat16 g_wh[4*D_MODEL*D_MODEL];
__device__ __align__(16) __nv_bfloat16 g_wl[4*D_MODEL*D_MODEL];
// QKV in bf16 hi/lo; Q pre-scaled by 1/8; V stored transposed [b,h,d,s]
__device__ __align__(16) __nv_bfloat16 g_qh[MTOT*D_MODEL];
__device__ __align__(16) __nv_bfloat16 g_ql[MTOT*D_MODEL];
__device__ __align__(16) __nv_bfloat16 g_kh[MTOT*D_MODEL];
__device__ __align__(16) __nv_bfloat16 g_kl[MTOT*D_MODEL];
__device__ __align__(16) __nv_bfloat16 g_vth[MTOT*D_MODEL];
__device__ __align__(16) __nv_bfloat16 g_vtl[MTOT*D_MODEL];

// ---------------- helpers ----------------
__device__ __forceinline__ uint32_t smem_u32(const void* p) {
    uint32_t a;
    asm("{ .reg .u64 t; cvta.to.shared.u64 t, %1; cvt.u32.u64 %0, t; }"
        : "=r"(a) : "l"(p));
    return a;
}
__device__ __forceinline__ void cp16(uint32_t s, const void* g) {
    asm volatile("cp.async.ca.shared.global [%0], [%1], 16;" :: "r"(s), "l"(g));
}
__device__ __forceinline__ void ldsm_x4(uint32_t r[4], uint32_t a) {
    asm volatile("ldmatrix.sync.aligned.m8n8.x4.shared.b16 {%0,%1,%2,%3}, [%4];"
        : "=r"(r[0]), "=r"(r[1]), "=r"(r[2]), "=r"(r[3]) : "r"(a));
}
__device__ __forceinline__ void mma16816(float d[4], const uint32_t a[4],
                                         uint32_t b0, uint32_t b1) {
    asm volatile("mma.sync.aligned.m16n8k16.row.col.f32.bf16.bf16.f32 "
        "{%0,%1,%2,%3}, {%4,%5,%6,%7}, {%8,%9}, {%0,%1,%2,%3};"
        : "+f"(d[0]), "+f"(d[1]), "+f"(d[2]), "+f"(d[3])
        : "r"(a[0]), "r"(a[1]), "r"(a[2]), "r"(a[3]), "r"(b0), "r"(b1));
}
// pack high-16 bits of two fp32 -> bf16x2 (low = x0). Truncation split.
__device__ __forceinline__ uint32_t pack_hi(float x0, float x1) {
    uint32_t r;
    asm("prmt.b32 %0, %1, %2, 0x7632;" : "=r"(r)
        : "r"(__float_as_uint(x0)), "r"(__float_as_uint(x1)));
    return r;
}
__device__ __forceinline__ uint32_t pack_lo(float x0, float x1) {
    float h0 = __uint_as_float(__float_as_uint(x0) & 0xFFFF0000u);
    float h1 = __uint_as_float(__float_as_uint(x1) & 0xFFFF0000u);
    uint32_t r;
    asm("cvt.rn.bf16x2.f32 %0, %1, %2;" : "=r"(r) : "f"(x1 - h1), "f"(x0 - h0));
    return r;
}
__device__ __forceinline__ void store_hl(__nv_bfloat16* H, __nv_bfloat16* L,
                                         size_t idx, float v) {
    uint32_t b = __float_as_uint(v);
    *(uint16_t*)(H + idx) = (uint16_t)(b >> 16);
    float hf = __uint_as_float(b & 0xFFFF0000u);
    L[idx] = __float2bfloat16_rn(v - hf);
}

// ---------------- bf16 hi/lo split ----------------
__global__ __launch_bounds__(256) void split_kernel(const float* __restrict__ s,
    __nv_bfloat16* __restrict__ h, __nv_bfloat16* __restrict__ l, int n)
{
    int i = (blockIdx.x * 256 + threadIdx.x) * 4;
    if (i >= n) return;
    float4 v = *(const float4*)(s + i);
    *(uint32_t*)(h + i)     = pack_hi(v.x, v.y);
    *(uint32_t*)(h + i + 2) = pack_hi(v.z, v.w);
    *(uint32_t*)(l + i)     = pack_lo(v.x, v.y);
    *(uint32_t*)(l + i + 2) = pack_lo(v.z, v.w);
}

// merged weight split: grid.y picks the source weight
__global__ __launch_bounds__(256) void wsplit_kernel(
    const float* __restrict__ w0, const float* __restrict__ w1,
    const float* __restrict__ w2, const float* __restrict__ w3)
{
    const int n = D_MODEL * D_MODEL;
    const float* src = (blockIdx.y == 0) ? w0 : (blockIdx.y == 1) ? w1 :
                       (blockIdx.y == 2) ? w2 : w3;
    __nv_bfloat16* h = g_wh + (size_t)blockIdx.y * n;
    __nv_bfloat16* l = g_wl + (size_t)blockIdx.y * n;
    int i = (blockIdx.x * 256 + threadIdx.x) * 4;
    if (i >= n) return;
    float4 v = *(const float4*)(src + i);
    *(uint32_t*)(h + i)     = pack_hi(v.x, v.y);
    *(uint32_t*)(h + i + 2) = pack_hi(v.z, v.w);
    *(uint32_t*)(l + i)     = pack_lo(v.x, v.y);
    *(uint32_t*)(l + i + 2) = pack_lo(v.z, v.w);
}

// ---------------- HMMA bf16x3 GEMM: C = A[M,K] @ W[N,K]^T ----------------
#define TSTRIDE 80
#define TILE_B  (128*TSTRIDE)
#define STAGE_B (4*TILE_B)
#define GEMM_SMEM (2*STAGE_B)
#define NKC (D_MODEL/32)

__device__ __forceinline__ void load_stage(uint32_t sb, int stage, int kc,
    const __nv_bfloat16* Ah, const __nv_bfloat16* Al,
    const __nv_bfloat16* Wh, const __nv_bfloat16* Wl, int m0, int n0)
{
    int k0 = kc * 32;
    uint32_t st = sb + stage * STAGE_B;
#pragma unroll
    for (int t = 0; t < 2; t++) {
        int chunk = threadIdx.x + t * 256;
        int row = chunk >> 2, cc = chunk & 3;
        uint32_t so = row * TSTRIDE + cc * 16;
        size_t ga = (size_t)(m0 + row) * D_MODEL + k0 + cc * 8;
        size_t gb = (size_t)(n0 + row) * D_MODEL + k0 + cc * 8;
        cp16(st + 0*TILE_B + so, Ah + ga);
        cp16(st + 1*TILE_B + so, Al + ga);
        cp16(st + 2*TILE_B + so, Wh + gb);
        cp16(st + 3*TILE_B + so, Wl + gb);
    }
    asm volatile("cp.async.commit_group;" ::: "memory");
}

__global__ __launch_bounds__(256, 2) void mma_gemm_kernel(float* __restrict__ out_o, int mode)
{
    extern __shared__ char smem[];
    uint32_t sb = smem_u32(smem);
    int tid = threadIdx.x, wid = tid >> 5, lane = tid & 31;

    int m0 = blockIdx.x * 128;
    int nb = blockIdx.y;
    int widx, n0;
    const __nv_bfloat16 *Ah, *Al;
    if (mode == 0) { widx = nb >> 3; n0 = (nb & 7) * 128; Ah = g_xh; Al = g_xl; }
    else           { widx = 3;       n0 = nb * 128;       Ah = g_ah; Al = g_al; }
    const __nv_bfloat16* Wh = g_wh + (size_t)widx * D_MODEL * D_MODEL;
    const __nv_bfloat16* Wl = g_wl + (size_t)widx * D_MODEL * D_MODEL;

    int wm = (wid & 1) * 64;
    int wn = (wid >> 1) * 32;

    float acc[4][4][4];
#pragma unroll
    for (int i = 0; i < 4; i++)
#pragma unroll
        for (int j = 0; j < 4; j++)
#pragma unroll
            for (int r = 0; r < 4; r++) acc[i][j][r] = 0.f;

    int lr = lane & 15;
    int lc = (lane >> 4) * 8;

    load_stage(sb, 0, 0, Ah, Al, Wh, Wl, m0, n0);

    int stage = 0;
    for (int kc = 0; kc < NKC; kc++) {
        if (kc + 1 < NKC) {
            load_stage(sb, stage ^ 1, kc + 1, Ah, Al, Wh, Wl, m0, n0);
            asm volatile("cp.async.wait_group 1;" ::: "memory");
        } else {
            asm volatile("cp.async.wait_group 0;" ::: "memory");
        }
        __syncthreads();

        uint32_t st = sb + stage * STAGE_B;
        uint32_t aH = st + 0*TILE_B, aL = st + 1*TILE_B;
        uint32_t bH = st + 2*TILE_B, bL = st + 3*TILE_B;

#pragma unroll
        for (int ks = 0; ks < 2; ks++) {
            int kb = ks * 16;
            uint32_t ahf[4][4], alf[4][4], bhf[2][4], blf[2][4];
#pragma unroll
            for (int mi = 0; mi < 4; mi++) {
                uint32_t ro = (uint32_t)(wm + mi*16 + lr) * TSTRIDE + (kb + lc) * 2;
                ldsm_x4(ahf[mi], aH + ro);
                ldsm_x4(alf[mi], aL + ro);
            }
#pragma unroll
            for (int p = 0; p < 2; p++) {
                uint32_t ro = (uint32_t)(wn + p*16 + lr) * TSTRIDE + (kb + lc) * 2;
                ldsm_x4(bhf[p], bH + ro);
                ldsm_x4(blf[p], bL + ro);
            }
#pragma unroll
            for (int mi = 0; mi < 4; mi++)
#pragma unroll
                for (int ni = 0; ni < 4; ni++) {
                    int p = ni >> 1, h = ni & 1;
                    mma16816(acc[mi][ni], ahf[mi], bhf[p][h], bhf[p][h+2]);
                    mma16816(acc[mi][ni], alf[mi], bhf[p][h], bhf[p][h+2]);
                    mma16816(acc[mi][ni], ahf[mi], blf[p][h], blf[p][h+2]);
                }
        }
        stage ^= 1;
        __syncthreads();
    }

    // Epilogue
    int qr = lane >> 2, qc = (lane & 3) * 2;
    float scl = (mode == 0 && widx == 0) ? 0.125f : 1.f;
#pragma unroll
    for (int mi = 0; mi < 4; mi++) {
#pragma unroll
        for (int ni = 0; ni < 4; ni++) {
            int r0 = m0 + wm + mi*16 + qr;
            int cN = n0 + wn + ni*8 + qc;
            float v0 = acc[mi][ni][0]*scl, v1 = acc[mi][ni][1]*scl;
            float v2 = acc[mi][ni][2]*scl, v3 = acc[mi][ni][3]*scl;
            if (mode == 0) {
                int h = cN >> 6, d = cN & 63;
                int b0 = r0 / SEQ, ss = r0 % SEQ;
                if (widx == 0) {
                    size_t a0 = (((size_t)(b0*NH + h))*SEQ + ss)*HD + d;
                    size_t a1 = a0 + 8*HD;
                    *(uint32_t*)(g_qh + a0) = pack_hi(v0, v1);
                    *(uint32_t*)(g_ql + a0) = pack_lo(v0, v1);
                    *(uint32_t*)(g_qh + a1) = pack_hi(v2, v3);
                    *(uint32_t*)(g_ql + a1) = pack_lo(v2, v3);
                } else if (widx == 1) {
                    size_t a0 = (((size_t)(b0*NH + h))*SEQ + ss)*HD + d;
                    size_t a1 = a0 + 8*HD;
                    *(uint32_t*)(g_kh + a0) = pack_hi(v0, v1);
                    *(uint32_t*)(g_kl + a0) = pack_lo(v0, v1);
                    *(uint32_t*)(g_kh + a1) = pack_hi(v2, v3);
                    *(uint32_t*)(g_kl + a1) = pack_lo(v2, v3);
                } else {
                    // V transposed: [b,h,d,s]
                    size_t base = ((size_t)(b0*NH + h)) * HD;
                    store_hl(g_vth, g_vtl, (base + d  )*SEQ + ss,     v0);
                    store_hl(g_vth, g_vtl, (base + d+1)*SEQ + ss,     v1);
                    store_hl(g_vth, g_vtl, (base + d  )*SEQ + ss + 8, v2);
                    store_hl(g_vth, g_vtl, (base + d+1)*SEQ + ss + 8, v3);
                }
            } else {
                float2* p0 = (float2*)(out_o + (size_t)r0 * D_MODEL + cN);
                float2* p1 = (float2*)(out_o + (size_t)(r0+8) * D_MODEL + cN);
                *p0 = make_float2(v0, v1);
                *p1 = make_float2(v2, v3);
            }
        }
    }
}

// ---------------- HMMA bf16x3 causal flash attention ----------------
// 128 q-rows per CTA, 8 warps x 16 rows, kv tiles of 128, double-buffered.
#define QSTR 144
#define KSTR 144
#define VSTR 272
#define AQ_H 0
#define AQ_L 18432
#define AK_BASE 36864
#define KBUF_SZ 71680        // Kh 18432 + Kl 18432 + Vth 17408 + Vtl 17408
#define ATTN_SMEM (AK_BASE + 2*KBUF_SZ)   // 180224

__device__ __forceinline__ void attn_load_kv(uint32_t sb, int buf, int t, int tid,
    const __nv_bfloat16* Kh, const __nv_bfloat16* Kl,
    const __nv_bfloat16* Vth, const __nv_bfloat16* Vtl)
{
    uint32_t kb = sb + AK_BASE + buf * KBUF_SZ;
#pragma unroll
    for (int p = 0; p < 4; p++) {
        int i = tid + p*256;          // 0..1023
        int row = i >> 3, c = i & 7;
        size_t g = (size_t)(t*128 + row)*HD + c*8;
        cp16(kb + row*KSTR + c*16, Kh + g);
        cp16(kb + 18432 + row*KSTR + c*16, Kl + g);
    }
#pragma unroll
    for (int p = 0; p < 4; p++) {
        int i = tid + p*256;
        int d = i >> 4, c = i & 15;
        size_t g = (size_t)d*SEQ + t*128 + c*8;
        cp16(kb + 36864 + d*VSTR + c*16, Vth + g);
        cp16(kb + 54272 + d*VSTR + c*16, Vtl + g);
    }
    asm volatile("cp.async.commit_group;" ::: "memory");
}

__global__ __launch_bounds__(256) void attn_mma_kernel()
{
    extern __shared__ char smem[];
    uint32_t sb = smem_u32(smem);
    int tid = threadIdx.x, wid = tid >> 5, lane = tid & 31;
    int qb = gridDim.x - 1 - blockIdx.x;        // long CTAs first
    int q0 = qb * 128, bh = blockIdx.y;

    const __nv_bfloat16* Qh  = g_qh  + (size_t)bh * SEQ * HD;
    const __nv_bfloat16* Ql  = g_ql  + (size_t)bh * SEQ * HD;
    const __nv_bfloat16* Kh  = g_kh  + (size_t)bh * SEQ * HD;
    const __nv_bfloat16* Kl  = g_kl  + (size_t)bh * SEQ * HD;
    const __nv_bfloat16* Vth = g_vth + (size_t)bh * HD * SEQ;
    const __nv_bfloat16* Vtl = g_vtl + (size_t)bh * HD * SEQ;

    // Q tile load (group 0)
#pragma unroll
    for (int p = 0; p < 4; p++) {
        int i = tid + p*256;
        int row = i >> 3, c = i & 7;
        size_t g = (size_t)(q0 + row)*HD + c*8;
        cp16(sb + AQ_H + row*QSTR + c*16, Qh + g);
        cp16(sb + AQ_L + row*QSTR + c*16, Ql + g);
    }
    asm volatile("cp.async.commit_group;" ::: "memory");

    attn_load_kv(sb, 0, 0, tid, Kh, Kl, Vth, Vtl);

    int lr = lane & 15, lc = (lane >> 4) * 8;
    float o[8][4];
#pragma unroll
    for (int j = 0; j < 8; j++)
#pragma unroll
        for (int e = 0; e < 4; e++) o[j][e] = 0.f;
    float m0r = -1e30f, m1r = -1e30f, l0 = 0.f, l1 = 0.f;

    uint32_t aqh[4][4], aql[4][4];   // persistent Q fragments

    int buf = 0;
    for (int t = 0; t <= qb; t++) {
        if (t < qb) {
            attn_load_kv(sb, buf ^ 1, t + 1, tid, Kh, Kl, Vth, Vtl);
            asm volatile("cp.async.wait_group 1;" ::: "memory");
        } else {
            asm volatile("cp.async.wait_group 0;" ::: "memory");
        }
        __syncthreads();
        uint32_t kb = sb + AK_BASE + buf * KBUF_SZ;

        if (t == 0) {   // Q fragments are loop-invariant: load once
#pragma unroll
            for (int kd = 0; kd < 4; kd++) {
                uint32_t ro = (uint32_t)(wid*16 + lr) * QSTR + (kd*16 + lc) * 2;
                ldsm_x4(aqh[kd], sb + AQ_H + ro);
                ldsm_x4(aql[kd], sb + AQ_L + ro);
            }
        }

        // S = Q K^T (bf16x3)
        float s[16][4];
#pragma unroll
        for (int j = 0; j < 16; j++)
#pragma unroll
            for (int e = 0; e < 4; e++) s[j][e] = 0.f;
#pragma unroll
        for (int p = 0; p < 8; p++) {
#pragma unroll
            for (int kd = 0; kd < 4; kd++) {
                uint32_t bh4[4], bl4[4];
                uint32_t ro = (uint32_t)(p*16 + lr) * KSTR + (kd*16 + lc) * 2;
                ldsm_x4(bh4, kb + ro);
                ldsm_x4(bl4, kb + 18432 + ro);
#pragma unroll
                for (int h = 0; h < 2; h++) {
                    mma16816(s[2*p+h], aqh[kd], bh4[h], bh4[h+2]);
                    mma16816(s[2*p+h], aql[kd], bh4[h], bh4[h+2]);
                    mma16816(s[2*p+h], aqh[kd], bl4[h], bl4[h+2]);
                }
            }
        }

        // causal mask on diagonal tile
        if (t == qb) {
            int r0l = wid*16 + (lane >> 2);
            int r1l = r0l + 8;
#pragma unroll
            for (int j = 0; j < 16; j++) {
                int c0 = 8*j + 2*(lane & 3);
                if (c0     > r0l) s[j][0] = -1e30f;
                if (c0 + 1 > r0l) s[j][1] = -1e30f;
                if (c0     > r1l) s[j][2] = -1e30f;
                if (c0 + 1 > r1l) s[j][3] = -1e30f;
            }
        }

        // online softmax (rows qr, qr+8; 4 lanes per row)
        float rm0 = -1e30f, rm1 = -1e30f;
#pragma unroll
        for (int j = 0; j < 16; j++) {
            rm0 = fmaxf(rm0, fmaxf(s[j][0], s[j][1]));
            rm1 = fmaxf(rm1, fmaxf(s[j][2], s[j][3]));
        }
        rm0 = fmaxf(rm0, __shfl_xor_sync(0xffffffffu, rm0, 1));
        rm0 = fmaxf(rm0, __shfl_xor_sync(0xffffffffu, rm0, 2));
        rm1 = fmaxf(rm1, __shfl_xor_sync(0xffffffffu, rm1, 1));
        rm1 = fmaxf(rm1, __shfl_xor_sync(0xffffffffu, rm1, 2));
        float mn0 = fmaxf(m0r, rm0), mn1 = fmaxf(m1r, rm1);
        float a0 = __expf(m0r - mn0), a1 = __expf(m1r - mn1);
        float sum0 = 0.f, sum1 = 0.f;
#pragma unroll
        for (int j = 0; j < 16; j++) {
            s[j][0] = __expf(s[j][0] - mn0);
            s[j][1] = __expf(s[j][1] - mn0);
            s[j][2] = __expf(s[j][2] - mn1);
            s[j][3] = __expf(s[j][3] - mn1);
            sum0 += s[j][0] + s[j][1];
            sum1 += s[j][2] + s[j][3];
        }
        sum0 += __shfl_xor_sync(0xffffffffu, sum0, 1);
        sum0 += __shfl_xor_sync(0xffffffffu, sum0, 2);
        sum1 += __shfl_xor_sync(0xffffffffu, sum1, 1);
        sum1 += __shfl_xor_sync(0xffffffffu, sum1, 2);
        l0 = l0 * a0 + sum0;  l1 = l1 * a1 + sum1;
        m0r = mn0;  m1r = mn1;
#pragma unroll
        for (int j = 0; j < 8; j++) {
            o[j][0] *= a0; o[j][1] *= a0; o[j][2] *= a1; o[j][3] *= a1;
        }

        // O += P @ V (bf16x3): pack P per-kk to keep register pressure low
#pragma unroll
        for (int kk = 0; kk < 8; kk++) {
            uint32_t ph[4], pl[4];
            ph[0] = pack_hi(s[2*kk][0],   s[2*kk][1]);
            ph[1] = pack_hi(s[2*kk][2],   s[2*kk][3]);
            ph[2] = pack_hi(s[2*kk+1][0], s[2*kk+1][1]);
            ph[3] = pack_hi(s[2*kk+1][2], s[2*kk+1][3]);
            pl[0] = pack_lo(s[2*kk][0],   s[2*kk][1]);
            pl[1] = pack_lo(s[2*kk][2],   s[2*kk][3]);
            pl[2] = pack_lo(s[2*kk+1][0], s[2*kk+1][1]);
            pl[3] = pack_lo(s[2*kk+1][2], s[2*kk+1][3]);
#pragma unroll
            for (int pd = 0; pd < 4; pd++) {
                uint32_t vh4[4], vl4[4];
                uint32_t ro = (uint32_t)(pd*16 + lr) * VSTR + (kk*16 + lc) * 2;
                ldsm_x4(vh4, kb + 36864 + ro);
                ldsm_x4(vl4, kb + 54272 + ro);
#pragma unroll
                for (int h = 0; h < 2; h++) {
                    mma16816(o[2*pd+h], ph, vh4[h], vh4[h+2]);
                    mma16816(o[2*pd+h], pl, vh4[h], vh4[h+2]);
                    mma16816(o[2*pd+h], ph, vl4[h], vl4[h+2]);
                }
            }
        }
        __syncthreads();
        buf ^= 1;
    }

    // epilogue: normalize, hi/lo split, write [B,S,D]
    float i0 = 1.f / l0, i1 = 1.f / l1;
    int b = bh >> 4, h = bh & 15;
    int s0 = q0 + wid*16 + (lane >> 2);
#pragma unroll
    for (int j = 0; j < 8; j++) {
        int d = h*64 + 8*j + 2*(lane & 3);
        float v0 = o[j][0]*i0, v1 = o[j][1]*i0;
        float v2 = o[j][2]*i1, v3 = o[j][3]*i1;
        size_t a0 = ((size_t)b*SEQ + s0) * D_MODEL + d;
        size_t a1 = a0 + (size_t)8 * D_MODEL;
        *(uint32_t*)(g_ah + a0) = pack_hi(v0, v1);
        *(uint32_t*)(g_al + a0) = pack_lo(v0, v1);
        *(uint32_t*)(g_ah + a1) = pack_hi(v2, v3);
        *(uint32_t*)(g_al + a1) = pack_lo(v2, v3);
    }
}

extern "C" void kernel_launch(void* const* d_in, const int* in_sizes, int n_in,
                              void* d_out, int out_size)
{
    const float* x  = (const float*)d_in[0];
    const float* wq = (const float*)d_in[1];
    const float* wk = (const float*)d_in[2];
    const float* wv = (const float*)d_in[3];
    const float* wo = (const float*)d_in[4];
    float* out = (float*)d_out;

    cudaFuncSetAttribute(mma_gemm_kernel,
                         cudaFuncAttributeMaxDynamicSharedMemorySize, GEMM_SMEM);
    cudaFuncSetAttribute(attn_mma_kernel,
                         cudaFuncAttributeMaxDynamicSharedMemorySize, ATTN_SMEM);

    __nv_bfloat16 *xh, *xl;
    cudaGetSymbolAddress((void**)&xh, g_xh);
    cudaGetSymbolAddress((void**)&xl, g_xl);

    const int NX = MTOT * D_MODEL;
    const int NW = D_MODEL * D_MODEL;

    split_kernel<<<NX/4/256, 256>>>(x, xh, xl, NX);
    dim3 gw(NW/4/256, 4);
    wsplit_kernel<<<gw, 256>>>(wq, wk, wv, wo);

    // QKV projection (writes bf16 hi/lo Q,K scaled + V transposed)
    dim3 g1(MTOT/128, 24);
    mma_gemm_kernel<<<g1, 256, GEMM_SMEM>>>(nullptr, 0);

    // tensor-core causal flash attention (writes bf16 hi/lo attn output)
    dim3 g2(SEQ/128, BATCH*NH);
    attn_mma_kernel<<<g2, 256, ATTN_SMEM>>>();

    // O-projection
    dim3 g3(MTOT/128, D_MODEL/128);
    mma_gemm_kernel<<<g3, 256, GEMM_SMEM>>>(out, 1);
}